// round 6
// baseline (speedup 1.0000x reference)
#include <cuda_runtime.h>

// Single-pass deterministic reduction with "last block finishes".
// 32-bit indexing (offsets < 2^31) + __launch_bounds__(256,8) to reach
// 32 regs -> 8 CTAs/SM -> 100% occupancy. GRID = 152 SMs * 8 = one wave.

#define GRID  1216
#define BLOCK 256

__device__ float          g_partials[GRID];
__device__ unsigned int   g_ticket = 0;

__global__ void __launch_bounds__(BLOCK, 8)
dist_mean_kernel(const float4* __restrict__ p, const float4* __restrict__ t,
                 int ngroups,            // each group = 3 float4 = 4 triplets
                 double inv_count,
                 float* __restrict__ out)
{
    float acc = 0.0f;
    const int stride = gridDim.x * blockDim.x;     // 311,296 < 2^31
    for (int g = blockIdx.x * blockDim.x + threadIdx.x;
         g < ngroups; g += stride) {
        const int base = 3 * g;                    // < 16.5M, fits int
        float4 pa = __ldcs(&p[base + 0]);
        float4 pb = __ldcs(&p[base + 1]);
        float4 pc = __ldcs(&p[base + 2]);
        float4 ta = __ldcs(&t[base + 0]);
        float4 tb = __ldcs(&t[base + 1]);
        float4 tc = __ldcs(&t[base + 2]);

        float d0x = pa.x - ta.x, d0y = pa.y - ta.y, d0z = pa.z - ta.z;
        float d1x = pa.w - ta.w, d1y = pb.x - tb.x, d1z = pb.y - tb.y;
        float d2x = pb.z - tb.z, d2y = pb.w - tb.w, d2z = pc.x - tc.x;
        float d3x = pc.y - tc.y, d3y = pc.z - tc.z, d3z = pc.w - tc.w;

        acc += sqrtf(fmaf(d0x, d0x, fmaf(d0y, d0y, d0z * d0z)));
        acc += sqrtf(fmaf(d1x, d1x, fmaf(d1y, d1y, d1z * d1z)));
        acc += sqrtf(fmaf(d2x, d2x, fmaf(d2y, d2y, d2z * d2z)));
        acc += sqrtf(fmaf(d3x, d3x, fmaf(d3y, d3y, d3z * d3z)));
    }

    // intra-warp reduce
    #pragma unroll
    for (int o = 16; o > 0; o >>= 1)
        acc += __shfl_down_sync(0xffffffffu, acc, o);

    __shared__ float sm[BLOCK / 32];
    if ((threadIdx.x & 31) == 0) sm[threadIdx.x >> 5] = acc;
    __syncthreads();

    __shared__ bool s_last;
    if (threadIdx.x < 32) {
        float v = (threadIdx.x < BLOCK / 32) ? sm[threadIdx.x] : 0.0f;
        #pragma unroll
        for (int o = 4; o > 0; o >>= 1)
            v += __shfl_down_sync(0xffffffffu, v, o);
        if (threadIdx.x == 0) {
            g_partials[blockIdx.x] = v;
            __threadfence();                          // partial visible before ticket
            unsigned int tk = atomicInc(&g_ticket, GRID - 1);
            s_last = (tk == GRID - 1);
        }
    }
    __syncthreads();

    if (!s_last) return;

    // ---- last block: deterministic final reduce ----
    // 256 threads, ceil(1216/256)=5 partials each, double accumulation.
    double dacc = 0.0;
    #pragma unroll
    for (int i = threadIdx.x; i < GRID; i += BLOCK)
        dacc += (double)g_partials[i];

    #pragma unroll
    for (int o = 16; o > 0; o >>= 1)
        dacc += __shfl_down_sync(0xffffffffu, dacc, o);

    __shared__ double dsm[BLOCK / 32];
    if ((threadIdx.x & 31) == 0) dsm[threadIdx.x >> 5] = dacc;
    __syncthreads();

    if (threadIdx.x == 0) {
        double v = 0.0;
        #pragma unroll
        for (int i = 0; i < BLOCK / 32; i++) v += dsm[i];
        out[0] = (float)(v * inv_count);
        // g_ticket wrapped to 0 via atomicInc's modulus — ready for next replay
    }
}

extern "C" void kernel_launch(void* const* d_in, const int* in_sizes, int n_in,
                              void* d_out, int out_size)
{
    const float4* pred = (const float4*)d_in[0];
    const float4* targ = (const float4*)d_in[1];
    float* out = (float*)d_out;

    const int    n_elem  = in_sizes[0];        // B * 63 = 66,060,288
    const int    ngroups = n_elem / 12;        // 4 triplets per group
    const long long n_dists = (long long)n_elem / 3;   // B * 21 distances
    const double inv_cnt = 1.0 / (double)n_dists;

    dist_mean_kernel<<<GRID, BLOCK>>>(pred, targ, ngroups, inv_cnt, out);
}

// round 7
// speedup vs baseline: 1.0532x; 1.0532x over previous
#include <cuda_runtime.h>

// Single-pass deterministic reduction with "last block finishes".
// R5 shape (natural regs, 6 CTAs/SM, one wave) + 32-bit byte-offset
// pointer-increment addressing: loads are LDG.E.128 [ptr+imm], no per-load
// IMAD, fewer live regs -> full 6-load batch stays in flight.

#define GRID  912           // 152 SMs * 6 resident CTAs
#define BLOCK 256

__device__ float          g_partials[GRID];
__device__ unsigned int   g_ticket = 0;

__global__ void __launch_bounds__(BLOCK)
dist_mean_kernel(const char* __restrict__ pbase, const char* __restrict__ tbase,
                 int niters,             // max grid-stride iterations
                 int nbytes,             // total bytes per input
                 double inv_count,
                 float* __restrict__ out)
{
    // Each thread owns groups of 48 bytes (4 triplets), strided by gridDim*blockDim*48.
    const int tid0   = (blockIdx.x * BLOCK + threadIdx.x) * 48;
    const int sbytes = GRID * BLOCK * 48;            // 48B per thread per iter

    const char* pp = pbase + tid0;
    const char* tt = tbase + tid0;
    int off = tid0;

    float acc = 0.0f;
    for (int i = 0; i < niters; i++) {
        if (off < nbytes) {
            float4 pa = __ldcs((const float4*)(pp +  0));
            float4 pb = __ldcs((const float4*)(pp + 16));
            float4 pc = __ldcs((const float4*)(pp + 32));
            float4 ta = __ldcs((const float4*)(tt +  0));
            float4 tb = __ldcs((const float4*)(tt + 16));
            float4 tc = __ldcs((const float4*)(tt + 32));

            float d0x = pa.x - ta.x, d0y = pa.y - ta.y, d0z = pa.z - ta.z;
            float d1x = pa.w - ta.w, d1y = pb.x - tb.x, d1z = pb.y - tb.y;
            float d2x = pb.z - tb.z, d2y = pb.w - tb.w, d2z = pc.x - tc.x;
            float d3x = pc.y - tc.y, d3y = pc.z - tc.z, d3z = pc.w - tc.w;

            acc += sqrtf(fmaf(d0x, d0x, fmaf(d0y, d0y, d0z * d0z)));
            acc += sqrtf(fmaf(d1x, d1x, fmaf(d1y, d1y, d1z * d1z)));
            acc += sqrtf(fmaf(d2x, d2x, fmaf(d2y, d2y, d2z * d2z)));
            acc += sqrtf(fmaf(d3x, d3x, fmaf(d3y, d3y, d3z * d3z)));
        }
        pp  += sbytes;
        tt  += sbytes;
        off += sbytes;
    }

    // intra-warp reduce
    #pragma unroll
    for (int o = 16; o > 0; o >>= 1)
        acc += __shfl_down_sync(0xffffffffu, acc, o);

    __shared__ float sm[BLOCK / 32];
    if ((threadIdx.x & 31) == 0) sm[threadIdx.x >> 5] = acc;
    __syncthreads();

    __shared__ bool s_last;
    if (threadIdx.x < 32) {
        float v = (threadIdx.x < BLOCK / 32) ? sm[threadIdx.x] : 0.0f;
        #pragma unroll
        for (int o = 4; o > 0; o >>= 1)
            v += __shfl_down_sync(0xffffffffu, v, o);
        if (threadIdx.x == 0) {
            g_partials[blockIdx.x] = v;
            __threadfence();                          // partial visible before ticket
            unsigned int tk = atomicInc(&g_ticket, GRID - 1);
            s_last = (tk == GRID - 1);
        }
    }
    __syncthreads();

    if (!s_last) return;

    // ---- last block: deterministic final reduce ----
    double dacc = 0.0;
    #pragma unroll
    for (int i = threadIdx.x; i < GRID; i += BLOCK)
        dacc += (double)g_partials[i];

    #pragma unroll
    for (int o = 16; o > 0; o >>= 1)
        dacc += __shfl_down_sync(0xffffffffu, dacc, o);

    __shared__ double dsm[BLOCK / 32];
    if ((threadIdx.x & 31) == 0) dsm[threadIdx.x >> 5] = dacc;
    __syncthreads();

    if (threadIdx.x == 0) {
        double v = 0.0;
        #pragma unroll
        for (int i = 0; i < BLOCK / 32; i++) v += dsm[i];
        out[0] = (float)(v * inv_count);
        // g_ticket wrapped to 0 via atomicInc's modulus — ready for next replay
    }
}

extern "C" void kernel_launch(void* const* d_in, const int* in_sizes, int n_in,
                              void* d_out, int out_size)
{
    const char* pred = (const char*)d_in[0];
    const char* targ = (const char*)d_in[1];
    float* out = (float*)d_out;

    const int n_elem  = in_sizes[0];               // B * 63 = 66,060,288
    const int nbytes  = n_elem * 4;                // 264,241,152 < 2^31
    const int per_it  = GRID * BLOCK * 48;         // bytes consumed per grid iteration
    const int niters  = (nbytes + per_it - 1) / per_it;
    const long long n_dists = (long long)n_elem / 3;
    const double inv_cnt = 1.0 / (double)n_dists;

    dist_mean_kernel<<<GRID, BLOCK>>>(pred, targ, niters, nbytes, inv_cnt, out);
}